// round 6
// baseline (speedup 1.0000x reference)
#include <cuda_runtime.h>
#include <math.h>

// MaskedNorm: B=8, T=4096, C=1024 fp32.
// Per-CHANNEL stats over masked tokens (ddof=1), out = m ? g*(y-mean)/(std+eps)+b : y.

#define CCH   1024
#define C4    (CCH / 4)      // 256 float4 per row
#define RTOT  32768          // B*T
#define R4TOT (RTOT / 4)     // 8192 row-quads
#define R8TOT (RTOT / 8)     // 4096 row-octets
#define NBLK  296            // reduce blocks: 2/SM x 148 SMs (1024 thr each)
#define MAXIT 7              // ceil(8192 / (296*4))
#define G3    1024           // normalize blocks: 4096/1024 = 4 iters exact
#define EPSF  1e-4f

__device__ __align__(16) float g_psum[NBLK][CCH];
__device__ __align__(16) float g_psq [NBLK][CCH];
__device__ int   g_pcnt[NBLK];
__device__ __align__(16) float g_scale[CCH];
__device__ __align__(16) float g_shift[CCH];

__device__ __forceinline__ void acc4(float4& s, float4& q, const float4 v) {
    s.x += v.x; s.y += v.y; s.z += v.z; s.w += v.w;
    q.x = fmaf(v.x, v.x, q.x);
    q.y = fmaf(v.y, v.y, q.y);
    q.z = fmaf(v.z, v.z, q.z);
    q.w = fmaf(v.w, v.w, q.w);
}

// ---------- Pass 1: per-channel partial sums over masked rows ----------
// 1024 threads = 4 row-groups x 256 channel-threads. All iteration masks are
// prefetched into registers first (independent loads), so the guarded y-loads
// pipeline across iterations instead of serializing on each mask fetch.
// Default-cached y loads: masked rows stay resident in L2 for pass 3.
__global__ __launch_bounds__(1024, 2)
void mn_reduce(const float4* __restrict__ y4, const int4* __restrict__ mask4) {
    __shared__ float4 ssum[4][256];
    __shared__ float4 ssq [4][256];
    __shared__ int    scnt[4];
    const int t = threadIdx.x & 255;   // channel slot (4 channels)
    const int g = threadIdx.x >> 8;    // row group 0..3
    const int p = blockIdx.x;
    const int base = p * 4 + g;        // first row-quad for this slot

    // Prefetch masks for all iterations (independent -> all in flight).
    int4 mks[MAXIT];
    #pragma unroll
    for (int i = 0; i < MAXIT; i++) {
        const int r4 = base + i * (NBLK * 4);
        mks[i] = (r4 < R4TOT) ? __ldg(&mask4[r4])
                              : make_int4(0, 0, 0, 0);
    }

    float4 s = make_float4(0.f, 0.f, 0.f, 0.f);
    float4 q = make_float4(0.f, 0.f, 0.f, 0.f);
    int cnt = 0;

    #pragma unroll
    for (int i = 0; i < MAXIT; i++) {
        const int r = (base + i * (NBLK * 4)) * 4;
        const int4 mk = mks[i];
        if (mk.x > 0) { acc4(s, q, __ldg(&y4[(r + 0) * C4 + t])); cnt++; }
        if (mk.y > 0) { acc4(s, q, __ldg(&y4[(r + 1) * C4 + t])); cnt++; }
        if (mk.z > 0) { acc4(s, q, __ldg(&y4[(r + 2) * C4 + t])); cnt++; }
        if (mk.w > 0) { acc4(s, q, __ldg(&y4[(r + 3) * C4 + t])); cnt++; }
    }
    ssum[g][t] = s;
    ssq [g][t] = q;
    if (t == 0) scnt[g] = cnt;   // cnt identical across t within a group
    __syncthreads();

    if (g == 0) {
        float4 S = ssum[0][t], Q = ssq[0][t];
        #pragma unroll
        for (int i = 1; i < 4; i++) {
            const float4 a = ssum[i][t], b = ssq[i][t];
            S.x += a.x; S.y += a.y; S.z += a.z; S.w += a.w;
            Q.x += b.x; Q.y += b.y; Q.z += b.z; Q.w += b.w;
        }
        reinterpret_cast<float4*>(g_psum[p])[t] = S;
        reinterpret_cast<float4*>(g_psq [p])[t] = Q;
        if (t == 0) g_pcnt[p] = scnt[0] + scnt[1] + scnt[2] + scnt[3];
    }
}

// ---------- Pass 2: fold partials -> scale/shift (parallel, coalesced) ----------
__global__ __launch_bounds__(256, 8)
void mn_stats(const float* __restrict__ gamma, const float* __restrict__ beta) {
    __shared__ float ssum[8][32];
    __shared__ float ssq [8][32];
    __shared__ int   sn;
    const int lane = threadIdx.x & 31;
    const int w    = threadIdx.x >> 5;
    const int c    = blockIdx.x * 32 + lane;

    float s = 0.0f, q = 0.0f;
    #pragma unroll 4
    for (int p = w; p < NBLK; p += 8) {
        s += g_psum[p][c];
        q += g_psq [p][c];
    }
    ssum[w][lane] = s;
    ssq [w][lane] = q;

    if (w == 0) {
        int n = 0;
        for (int p = lane; p < NBLK; p += 32) n += g_pcnt[p];
        #pragma unroll
        for (int o = 16; o; o >>= 1) n += __shfl_down_sync(0xffffffffu, n, o);
        if (lane == 0) sn = n;
    }
    __syncthreads();

    if (w == 0) {
        float S = 0.0f, Q = 0.0f;
        #pragma unroll
        for (int i = 0; i < 8; i++) { S += ssum[i][lane]; Q += ssq[i][lane]; }
        const float nf   = (float)sn;
        const float mean = S / nf;
        const float var  = (Q - S * S / nf) / (nf - 1.0f);
        const float sd   = sqrtf(var);
        const float sc   = __ldg(&gamma[c]) / (sd + EPSF);
        g_scale[c] = sc;
        g_shift[c] = __ldg(&beta[c]) - mean * sc;   // out = fma(y, sc, shift)
    }
}

// ---------- Pass 3: normalize (float4, 8 rows/iter, branch-free) ----------
// Per-row predicate + FSEL instead of if{} bodies (no BSSY/BSYNC envelopes).
// __ldcs: consume-and-evict (masked rows were staged into L2 by pass 1 and
// are dead after this read). Streaming stores.
__device__ __forceinline__ float4 sel_norm(const float4 v, const float4 sc,
                                           const float4 sh, const bool m) {
    float4 o;
    o.x = m ? fmaf(v.x, sc.x, sh.x) : v.x;
    o.y = m ? fmaf(v.y, sc.y, sh.y) : v.y;
    o.z = m ? fmaf(v.z, sc.z, sh.z) : v.z;
    o.w = m ? fmaf(v.w, sc.w, sh.w) : v.w;
    return o;
}

__global__ __launch_bounds__(256, 8)
void mn_norm(const float4* __restrict__ y4, const int4* __restrict__ mask4,
             float4* __restrict__ out4) {
    const int t = threadIdx.x;
    const float4 sc = reinterpret_cast<const float4*>(g_scale)[t];
    const float4 sh = reinterpret_cast<const float4*>(g_shift)[t];

    #pragma unroll 1
    for (int r8 = blockIdx.x; r8 < R8TOT; r8 += G3) {
        const int r = r8 * 8;
        const int4 ma = __ldg(&mask4[r8 * 2 + 0]);
        const int4 mb = __ldg(&mask4[r8 * 2 + 1]);
        const float4 v0 = __ldcs(&y4[(r + 0) * C4 + t]);
        const float4 v1 = __ldcs(&y4[(r + 1) * C4 + t]);
        const float4 v2 = __ldcs(&y4[(r + 2) * C4 + t]);
        const float4 v3 = __ldcs(&y4[(r + 3) * C4 + t]);
        const float4 v4 = __ldcs(&y4[(r + 4) * C4 + t]);
        const float4 v5 = __ldcs(&y4[(r + 5) * C4 + t]);
        const float4 v6 = __ldcs(&y4[(r + 6) * C4 + t]);
        const float4 v7 = __ldcs(&y4[(r + 7) * C4 + t]);

        __stcs(&out4[(r + 0) * C4 + t], sel_norm(v0, sc, sh, ma.x > 0));
        __stcs(&out4[(r + 1) * C4 + t], sel_norm(v1, sc, sh, ma.y > 0));
        __stcs(&out4[(r + 2) * C4 + t], sel_norm(v2, sc, sh, ma.z > 0));
        __stcs(&out4[(r + 3) * C4 + t], sel_norm(v3, sc, sh, ma.w > 0));
        __stcs(&out4[(r + 4) * C4 + t], sel_norm(v4, sc, sh, mb.x > 0));
        __stcs(&out4[(r + 5) * C4 + t], sel_norm(v5, sc, sh, mb.y > 0));
        __stcs(&out4[(r + 6) * C4 + t], sel_norm(v6, sc, sh, mb.z > 0));
        __stcs(&out4[(r + 7) * C4 + t], sel_norm(v7, sc, sh, mb.w > 0));
    }
}

extern "C" void kernel_launch(void* const* d_in, const int* in_sizes, int n_in,
                              void* d_out, int out_size) {
    const float* y     = (const float*)d_in[0];
    const int*   mask  = (const int*)  d_in[1];
    const float* gamma = (const float*)d_in[2];
    const float* beta  = (const float*)d_in[3];
    float*       out   = (float*)d_out;

    mn_reduce<<<NBLK, 1024>>>((const float4*)y, (const int4*)mask);
    mn_stats<<<32, 256>>>(gamma, beta);
    mn_norm<<<G3, 256>>>((const float4*)y, (const int4*)mask, (float4*)out);
}

// round 7
// speedup vs baseline: 1.1447x; 1.1447x over previous
#include <cuda_runtime.h>
#include <math.h>

// MaskedNorm: B=8, T=4096, C=1024 fp32.
// Per-CHANNEL stats over masked tokens (ddof=1), out = m ? g*(y-mean)/(std+eps)+b : y.

#define CCH   1024
#define C4    (CCH / 4)      // 256 float4 per row
#define RTOT  32768          // B*T
#define R4TOT (RTOT / 4)     // 8192 row-quads
#define R2TOT (RTOT / 2)     // 16384 row-pairs
#define NBLK  296            // reduce blocks: 2/SM x 148 SMs (1024 thr each)
#define G3    2048           // normalize blocks: 16384/2048 = 8 iters exact
#define EPSF  1e-4f

__device__ __align__(16) float g_psum[NBLK][CCH];
__device__ __align__(16) float g_psq [NBLK][CCH];
__device__ int   g_pcnt[NBLK];
__device__ __align__(16) float g_scale[CCH];
__device__ __align__(16) float g_shift[CCH];

__device__ __forceinline__ void acc4(float4& s, float4& q, const float4 v) {
    s.x += v.x; s.y += v.y; s.z += v.z; s.w += v.w;
    q.x = fmaf(v.x, v.x, q.x);
    q.y = fmaf(v.y, v.y, q.y);
    q.z = fmaf(v.z, v.z, q.z);
    q.w = fmaf(v.w, v.w, q.w);
}

// ---------- Pass 1: per-channel partial sums over masked rows ----------
// (R4 version — best measured: 15.0us.) 1024 threads = 4 row-groups x 256
// channel-threads. Default-cached y loads stage masked rows in L2 for pass 3.
__global__ __launch_bounds__(1024, 2)
void mn_reduce(const float4* __restrict__ y4, const int4* __restrict__ mask4) {
    __shared__ float4 ssum[4][256];
    __shared__ float4 ssq [4][256];
    __shared__ int    scnt[4];
    const int t = threadIdx.x & 255;   // channel slot (4 channels)
    const int g = threadIdx.x >> 8;    // row group 0..3
    const int p = blockIdx.x;

    float4 s = make_float4(0.f, 0.f, 0.f, 0.f);
    float4 q = make_float4(0.f, 0.f, 0.f, 0.f);
    int cnt = 0;

    for (int r4 = p * 4 + g; r4 < R4TOT; r4 += NBLK * 4) {
        const int  r  = r4 * 4;
        const int4 mk = __ldg(&mask4[r4]);
        if (mk.x > 0) { acc4(s, q, __ldg(&y4[(r + 0) * C4 + t])); cnt++; }
        if (mk.y > 0) { acc4(s, q, __ldg(&y4[(r + 1) * C4 + t])); cnt++; }
        if (mk.z > 0) { acc4(s, q, __ldg(&y4[(r + 2) * C4 + t])); cnt++; }
        if (mk.w > 0) { acc4(s, q, __ldg(&y4[(r + 3) * C4 + t])); cnt++; }
    }
    ssum[g][t] = s;
    ssq [g][t] = q;
    if (t == 0) scnt[g] = cnt;   // cnt identical across t within a group
    __syncthreads();

    if (g == 0) {
        float4 S = ssum[0][t], Q = ssq[0][t];
        #pragma unroll
        for (int i = 1; i < 4; i++) {
            const float4 a = ssum[i][t], b = ssq[i][t];
            S.x += a.x; S.y += a.y; S.z += a.z; S.w += a.w;
            Q.x += b.x; Q.y += b.y; Q.z += b.z; Q.w += b.w;
        }
        reinterpret_cast<float4*>(g_psum[p])[t] = S;
        reinterpret_cast<float4*>(g_psq [p])[t] = Q;
        if (t == 0) g_pcnt[p] = scnt[0] + scnt[1] + scnt[2] + scnt[3];
    }
}

// ---------- Pass 2: fold partials -> scale/shift (parallel, coalesced) ----------
__global__ __launch_bounds__(256, 8)
void mn_stats(const float* __restrict__ gamma, const float* __restrict__ beta) {
    __shared__ float ssum[8][32];
    __shared__ float ssq [8][32];
    __shared__ int   sn;
    const int lane = threadIdx.x & 31;
    const int w    = threadIdx.x >> 5;
    const int c    = blockIdx.x * 32 + lane;

    float s = 0.0f, q = 0.0f;
    #pragma unroll 4
    for (int p = w; p < NBLK; p += 8) {
        s += g_psum[p][c];
        q += g_psq [p][c];
    }
    ssum[w][lane] = s;
    ssq [w][lane] = q;

    if (w == 0) {
        int n = 0;
        for (int p = lane; p < NBLK; p += 32) n += g_pcnt[p];
        #pragma unroll
        for (int o = 16; o; o >>= 1) n += __shfl_down_sync(0xffffffffu, n, o);
        if (lane == 0) sn = n;
    }
    __syncthreads();

    if (w == 0) {
        float S = 0.0f, Q = 0.0f;
        #pragma unroll
        for (int i = 0; i < 8; i++) { S += ssum[i][lane]; Q += ssq[i][lane]; }
        const float nf   = (float)sn;
        const float mean = S / nf;
        const float var  = (Q - S * S / nf) / (nf - 1.0f);
        const float sd   = sqrtf(var);
        const float sc   = __ldg(&gamma[c]) / (sd + EPSF);
        g_scale[c] = sc;
        g_shift[c] = __ldg(&beta[c]) - mean * sc;   // out = fma(y, sc, shift)
    }
}

// ---------- Pass 3: normalize (float4, 2 rows/iter, low MLP_p1) ----------
// Small front-batch (1 mask + 2 y loads) to stay under the cross-CTA
// L1tex-queue contention threshold (oe*MLP_p1 ~ 16). Guarded FMA bodies,
// default-cached loads (L2 hits from pass 1), streaming stores.
__global__ __launch_bounds__(256, 8)
void mn_norm(const float4* __restrict__ y4, const int* __restrict__ mask,
             float4* __restrict__ out4) {
    const int t = threadIdx.x;
    const float4 sc = reinterpret_cast<const float4*>(g_scale)[t];
    const float4 sh = reinterpret_cast<const float4*>(g_shift)[t];

    #pragma unroll 1
    for (int r2 = blockIdx.x; r2 < R2TOT; r2 += G3) {
        const int r  = r2 * 2;
        const int m0 = __ldg(&mask[r + 0]);
        const int m1 = __ldg(&mask[r + 1]);
        float4 v0 = __ldg(&y4[(r + 0) * C4 + t]);
        float4 v1 = __ldg(&y4[(r + 1) * C4 + t]);
        if (m0 > 0) {
            v0.x = fmaf(v0.x, sc.x, sh.x); v0.y = fmaf(v0.y, sc.y, sh.y);
            v0.z = fmaf(v0.z, sc.z, sh.z); v0.w = fmaf(v0.w, sc.w, sh.w);
        }
        __stcs(&out4[(r + 0) * C4 + t], v0);
        if (m1 > 0) {
            v1.x = fmaf(v1.x, sc.x, sh.x); v1.y = fmaf(v1.y, sc.y, sh.y);
            v1.z = fmaf(v1.z, sc.z, sh.z); v1.w = fmaf(v1.w, sc.w, sh.w);
        }
        __stcs(&out4[(r + 1) * C4 + t], v1);
    }
}

extern "C" void kernel_launch(void* const* d_in, const int* in_sizes, int n_in,
                              void* d_out, int out_size) {
    const float* y     = (const float*)d_in[0];
    const int*   mask  = (const int*)  d_in[1];
    const float* gamma = (const float*)d_in[2];
    const float* beta  = (const float*)d_in[3];
    float*       out   = (float*)d_out;

    mn_reduce<<<NBLK, 1024>>>((const float4*)y, (const int4*)mask);
    mn_stats<<<32, 256>>>(gamma, beta);
    mn_norm<<<G3, 256>>>((const float4*)y, mask, (float4*)out);
}